// round 4
// baseline (speedup 1.0000x reference)
#include <cuda_runtime.h>
#include <stdint.h>

static constexpr int L     = 4096;   // MAXLEN
static constexpr int LIMIT = 256;    // band width
static constexpr int BATCH = 4;
static constexpr int ROWS_PER_BLOCK = 16;
static constexpr int QUADS_PER_LOAD_ROW = 65;   // 260 floats covers any 4B shift of 256
static constexpr int SMEM_ROW_QUADS = 66;       // +1 quad pad
static constexpr long long TOTAL_QUADS = (long long)BATCH * L * (L / 4); // quads in x

// out[b,i,j] = x[b,i,i+j] if i+j < L else 0.
// Stage 1: aligned LDG.128 of each row's band (rounded down to 16B) into smem.
// Stage 2: shifted conflict-free LDS.32 + masked coalesced STG.32.
__global__ __launch_bounds__(256) void band_gather_kernel(
    const float4* __restrict__ x4, float* __restrict__ out)
{
    __shared__ float4 sm[ROWS_PER_BLOCK * SMEM_ROW_QUADS];

    const int tid = threadIdx.x;
    const int block_row0 = blockIdx.x * ROWS_PER_BLOCK;   // global row = b*L + i

    // ---- Load phase: 16 rows * 65 aligned quads = 1040 LDG.128 ----
    const int total_loads = ROWS_PER_BLOCK * QUADS_PER_LOAD_ROW;
    #pragma unroll
    for (int k = 0; k < 5; k++) {
        int idx = k * 256 + tid;
        if (idx < total_loads) {
            int r = idx / QUADS_PER_LOAD_ROW;
            int t = idx - r * QUADS_PER_LOAD_ROW;
            int grow = block_row0 + r;
            int i = grow & (L - 1);
            long long gq = (long long)grow * (L / 4) + (i >> 2) + t;
            if (gq >= TOTAL_QUADS) gq = TOTAL_QUADS - 1;   // clamp; masked later
            sm[r * SMEM_ROW_QUADS + t] = x4[gq];
        }
    }
    __syncthreads();

    // ---- Store phase: one row per iteration, j = tid ----
    const float* smf = (const float*)sm;
    #pragma unroll
    for (int r = 0; r < ROWS_PER_BLOCK; r++) {
        int grow = block_row0 + r;
        int i = grow & (L - 1);
        int j = tid;                                  // LIMIT == blockDim == 256
        float v = smf[r * (SMEM_ROW_QUADS * 4) + (i & 3) + j];
        out[(size_t)grow * LIMIT + j] = (i + j < L) ? v : 0.0f;
    }
}

extern "C" void kernel_launch(void* const* d_in, const int* in_sizes, int n_in,
                              void* d_out, int out_size)
{
    const float4* x4 = (const float4*)d_in[0];
    float* out = (float*)d_out;

    int blocks = (BATCH * L) / ROWS_PER_BLOCK;   // 1024
    band_gather_kernel<<<blocks, 256>>>(x4, out);
}